// round 16
// baseline (speedup 1.0000x reference)
#include <cuda_runtime.h>
#include <cuda_fp16.h>
#include <cstdint>
#include <math.h>

#define T_ 2032
#define TKV_ 2112            // keys padded to 22 * 96
#define D_ 1408
#define NH_ 1408
#define NHEADS_ 16
#define HD_ 88
#define HP_ 96
#define GK_ 1408
#define GN_ 1408
#define NCHUNK 88            // 1408 / 16
#define SL2 0.15379179f      // 88^-0.5 * log2(e)

// Scratch (allocation-free rule: device globals), all fp16
__device__ __half g_xf[T_ * GK_];                 // x rounded (A of QKV)
__device__ __half g_af[T_ * GK_];                 // attn-out rounded (A of out-proj)
__device__ __half g_wf[4L * GK_ * GN_];           // Wq|Wk|Wv|Wo rounded
#define PADSZ (TKV_ * NHEADS_ * HP_)
__device__ __half g_qf[PADSZ];                    // pre-scaled by SL2; col89 = -8
__device__ __half g_kf[PADSZ];                    // col89 = 1
__device__ __half g_vf[PADSZ];                    // col88 = 1 (row-sum column)

// ===========================================================================
// Helpers (baseline PTX — compute_103 safe)
// ===========================================================================
__device__ __forceinline__ uint32_t smem_u32(const void* p) {
    uint32_t a;
    asm("{ .reg .u64 t; cvta.to.shared.u64 t, %1; cvt.u32.u64 %0, t; }"
        : "=r"(a) : "l"(p));
    return a;
}
__device__ __forceinline__ void ldsm_x4(uint32_t* r, uint32_t addr) {
    asm volatile("ldmatrix.sync.aligned.m8n8.x4.shared.b16 {%0,%1,%2,%3}, [%4];"
                 : "=r"(r[0]), "=r"(r[1]), "=r"(r[2]), "=r"(r[3]) : "r"(addr));
}
__device__ __forceinline__ void ldsm_x4_t(uint32_t* r, uint32_t addr) {
    asm volatile("ldmatrix.sync.aligned.m8n8.x4.trans.shared.b16 {%0,%1,%2,%3}, [%4];"
                 : "=r"(r[0]), "=r"(r[1]), "=r"(r[2]), "=r"(r[3]) : "r"(addr));
}
__device__ __forceinline__ void mma_f16(float* d, const uint32_t* a, const uint32_t* b) {
    asm volatile(
        "mma.sync.aligned.m16n8k16.row.col.f32.f16.f16.f32 "
        "{%0,%1,%2,%3}, {%4,%5,%6,%7}, {%8,%9}, {%0,%1,%2,%3};"
        : "+f"(d[0]), "+f"(d[1]), "+f"(d[2]), "+f"(d[3])
        : "r"(a[0]), "r"(a[1]), "r"(a[2]), "r"(a[3]), "r"(b[0]), "r"(b[1]));
}
__device__ __forceinline__ uint32_t ex2h2(uint32_t a) {
    uint32_t y;
    asm("ex2.approx.f16x2 %0, %1;" : "=r"(y) : "r"(a));
    return y;
}
__device__ __forceinline__ void cp16(uint32_t dst, const void* src) {
    asm volatile("cp.async.cg.shared.global [%0], [%1], 16;"
                 :: "r"(dst), "l"(src) : "memory");
}
__device__ __forceinline__ void cp16z(uint32_t dst, const void* src, uint32_t srcsz) {
    asm volatile("cp.async.cg.shared.global [%0], [%1], 16, %2;"
                 :: "r"(dst), "l"(src), "r"(srcsz) : "memory");
}
#define CP_COMMIT() asm volatile("cp.async.commit_group;" ::: "memory")
#define CP_WAIT(n)  asm volatile("cp.async.wait_group %0;" :: "n"(n) : "memory")

__device__ __forceinline__ uint32_t pack2h(float x, float y) {
    return (uint32_t)__half_as_ushort(__float2half_rn(x))
         | ((uint32_t)__half_as_ushort(__float2half_rn(y)) << 16);
}

// ===========================================================================
// Conversion: x + 4 weights in one launch (pure bandwidth)
// ===========================================================================
__global__ void cvt_all_kernel(const float* __restrict__ x,
                               const float* __restrict__ w0, const float* __restrict__ w1,
                               const float* __restrict__ w2, const float* __restrict__ w3,
                               __half* __restrict__ xf, __half* __restrict__ wf)
{
    long i = (long)blockIdx.x * 256 + threadIdx.x;
    const int n2x = T_ * GK_ / 2;
    const long n2w = (long)GK_ * GN_ / 2;
    if (i < n2x) {
        float2 v = ((const float2*)x)[i];
        ((uint32_t*)xf)[i] = pack2h(v.x, v.y);
    } else {
        long j = i - n2x;
        if (j >= 4 * n2w) return;
        int which = (int)(j / n2w);
        long r = j - (long)which * n2w;
        const float* src = which == 0 ? w0 : which == 1 ? w1 : which == 2 ? w2 : w3;
        float2 v = ((const float2*)src)[r];
        ((uint32_t*)wf)[j] = pack2h(v.x, v.y);
    }
}

// ===========================================================================
// Pad + softmax side-channel constants (unchanged from R15)
// ===========================================================================
#define PAD_R1 (TKV_ * NHEADS_ * 4)
#define PAD_R2 ((TKV_ - T_) * NHEADS_ * 44)
__global__ void pad_kernel(__half* a0, __half* a1, __half* a2)
{
    int i = blockIdx.x * 256 + threadIdx.x;
    uint32_t idx;
    uint32_t qv = 0, kv = 0, vv = 0;
    if (i < PAD_R1) {
        int th = i >> 2, off = i & 3;
        idx = (uint32_t)th * 48 + 44 + off;
        if (off == 0) {                 // cols (88, 89)
            qv = pack2h(0.f, -8.f);
            kv = pack2h(0.f, 1.f);
            vv = pack2h(1.f, 0.f);
        }
    } else if (i < PAD_R1 + PAD_R2) {
        int j = i - PAD_R1;
        int t = T_ + j / (NHEADS_ * 44);
        int r = j % (NHEADS_ * 44);
        int head = r / 44, p = r % 44;
        idx = (uint32_t)(t * NHEADS_ + head) * 48 + p;
    } else return;
    ((uint32_t*)a0)[idx] = qv; ((uint32_t*)a1)[idx] = kv;
    ((uint32_t*)a2)[idx] = vv;
}

// ===========================================================================
// HMMA GEMM v10: 64x128 CTA tile (fine-grain wave packing), occ 3.
// 8 warps x (16x64), pure fp16 1-term, cp.async 4-stage pipeline.
// ===========================================================================
struct G3 {
    const __half* bw[3];
    const float* bias[3];
    __half* o0[3];
    float* c0;
    int mode;
};

#define AS_ST 24        // halfs per A smem row (48 B)
#define BS_ST 136       // halfs per B smem row (272 B)
#define ABYT 3072       // A stage bytes: 64 x 48
#define GBUF 7424       // ABYT + 4352
#define NSTG 4
#define GEMM_SMEM (NSTG * GBUF)   // 29696

__global__ __launch_bounds__(256, 3)
void hmma_gemm10_kernel(const __half* __restrict__ Ah,
                        const float* __restrict__ fc, G3 g)
{
    extern __shared__ char smg[];
    uint32_t sb = smem_u32(smg);

    const int tid = threadIdx.x;
    const int wid = tid >> 5, lane = tid & 31;
    const int wm = wid & 3, wn = wid >> 2;     // 4 row groups x 2 col groups
    const int bm = blockIdx.y * 64;
    const int which = blockIdx.x / 11;
    const int bn = (blockIdx.x - which * 11) * 128;

    // staging: A 128 ops (tid<128), B 256 ops (all threads)
    const int arow = tid >> 1;                 // 0..127 (use <64 via tid<128)
    const int acs = (tid & 1) * 8;
    const int brow = tid >> 4;
    const int bcs = (tid & 15) * 8;
    const bool hasA = tid < 128;
    const uint32_t aok = (hasA && (bm + arow) < T_) ? 16u : 0u;

    const __half* ag = Ah + (long)(bm + arow) * GK_ + acs;
    const __half* bg = g.bw[which] + (long)brow * GN_ + bn + bcs;

    const uint32_t a_dst = sb + (uint32_t)((arow * AS_ST + acs) * 2);
    const uint32_t b_dst = sb + ABYT + (uint32_t)((brow * BS_ST + bcs) * 2);

    float acc[8][4];
#pragma unroll
    for (int j = 0; j < 8; j++)
#pragma unroll
        for (int e = 0; e < 4; e++) acc[j][e] = 0.f;

    const uint32_t aoff = (uint32_t)((wm * 16 + (lane & 15)) * 48 + (lane >> 4) * 16);
    const uint32_t boff = (uint32_t)((lane & 15) * 272 + wn * 128 + (lane >> 4) * 16);

#pragma unroll
    for (int c = 0; c < 3; c++) {
        if (hasA) cp16z(a_dst + c * GBUF, ag + c * 16, aok);
        cp16(b_dst + c * GBUF, bg + (long)(c * 16) * GN_);
        CP_COMMIT();
    }

    for (int c = 0; c < NCHUNK; c++) {
        const int s = c & 3;
        if (c <= NCHUNK - 3)      { CP_WAIT(2); }
        else if (c == NCHUNK - 2) { CP_WAIT(1); }
        else                      { CP_WAIT(0); }
        __syncthreads();

        if (c + 3 < NCHUNK) {
            const uint32_t st = (uint32_t)(((c + 3) & 3) * GBUF);
            if (hasA) cp16z(a_dst + st, ag + (c + 3) * 16, aok);
            cp16(b_dst + st, bg + (long)((c + 3) * 16) * GN_);
            CP_COMMIT();
        }

        uint32_t ah[4], bh[4][4];
        {
            uint32_t a_b = sb + s * GBUF;
            ldsm_x4(ah, a_b + aoff);
            uint32_t b_b = sb + s * GBUF + ABYT;
#pragma unroll
            for (int j2 = 0; j2 < 4; j2++)
                ldsm_x4_t(bh[j2], b_b + boff + j2 * 32);
        }
#pragma unroll
        for (int j = 0; j < 8; j++)
            mma_f16(acc[j], ah, &bh[j >> 1][(j & 1) * 2]);
    }

    // ---- epilogue ----
    const float* bias = g.bias[which];
    if (g.mode == 1) {
        float* C = g.c0;
        int r0 = bm + wm * 16 + (lane >> 2);
#pragma unroll
        for (int j = 0; j < 8; j++) {
            int cc = bn + wn * 64 + j * 8 + (lane & 3) * 2;
            float b0 = bias[cc], b1 = bias[cc + 1];
            if (r0 < T_) {
                float* p = C + (long)r0 * GN_ + cc;
                p[0] = acc[j][0] + b0;
                p[1] = acc[j][1] + b1;
            }
            if (r0 + 8 < T_) {
                float* p = C + (long)(r0 + 8) * GN_ + cc;
                p[0] = acc[j][2] + b0;
                p[1] = acc[j][3] + b1;
            }
        }
    } else {
        __half* o0 = g.o0[which];
        const bool dorope = (which < 2);
        const float qs = (which == 0) ? SL2 : 1.0f;
        int r0 = bm + wm * 16 + (lane >> 2);
#pragma unroll
        for (int j = 0; j < 8; j++) {
            int cc = bn + wn * 64 + j * 8 + (lane & 3) * 2;
            float b0 = bias[cc], b1 = bias[cc + 1];
            int head = cc / HD_;
            int h = cc - head * HD_;
#pragma unroll
            for (int half = 0; half < 2; half++) {
                int t = r0 + half * 8;
                if (t >= T_) continue;
                float v0 = acc[j][2 * half + 0] + b0;
                float v1 = acc[j][2 * half + 1] + b1;
                float r0v = v0, r1v = v1;
                if (dorope) {
                    float cs = fc[t * HD_ + h];
                    float sn = fc[t * HD_ + h + 1];
                    r0v = v0 * cs - v1 * sn;
                    r1v = v0 * sn + v1 * cs;
                }
                r0v *= qs; r1v *= qs;
                uint32_t dst = (uint32_t)(t * NHEADS_ + head) * HP_ + h;
                *(uint32_t*)(o0 + dst) = pack2h(r0v, r1v);
            }
        }
    }
}

// ===========================================================================
// HMMA flash attention v6 (unchanged from R15 — at MMA floor)
// ===========================================================================
#define SSTB 208
#define KVARR 19968
#define KVSTG (2 * KVARR)
#define ATT_SMEM (2 * KVSTG) // 79872
#define NBLK 22

__global__ __launch_bounds__(256, 2)
void hmma_attn_kernel(const __half* __restrict__ qf,
                      const __half* __restrict__ kf,
                      const __half* __restrict__ vf,
                      __half* __restrict__ Of)
{
    extern __shared__ char sm[];
    uint32_t sbase = smem_u32(sm);
    const int tid = threadIdx.x;
    const int wid = tid >> 5;
    const int lane = tid & 31;
    const int n = blockIdx.y;
    const int q0 = blockIdx.x * 128;

#pragma unroll
    for (int it = 0; it < 6; it++) {
        int id = tid + it * 256;
        int row = id / 12;
        int c   = id - row * 12;
        const __half* src = qf + ((long)(q0 + row) * NHEADS_ + n) * HP_ + c * 8;
        cp16(sbase + row * SSTB + c * 16, src);
    }
    CP_COMMIT();
    CP_WAIT(0);
    __syncthreads();

    uint32_t qh[6][4];
    {
        uint32_t qaddr = sbase + (wid * 16 + (lane & 15)) * SSTB + (lane >> 4) * 16;
#pragma unroll
        for (int kk = 0; kk < 6; kk++)
            ldsm_x4(qh[kk], qaddr + kk * 32);
    }
    __syncthreads();

    float oacc[12][4];
#pragma unroll
    for (int f = 0; f < 12; f++)
#pragma unroll
        for (int e = 0; e < 4; e++) oacc[f][e] = 0.f;

#pragma unroll
    for (int it = 0; it < 9; it++) {
        int id = tid + it * 256;
        int arr = id / 1152;
        int rem = id - arr * 1152;
        int row = rem / 12;
        int c   = rem - row * 12;
        const __half* src = (arr == 0 ? kf : vf)
            + ((long)row * NHEADS_ + n) * HP_ + c * 8;
        cp16(sbase + arr * KVARR + row * SSTB + c * 16, src);
    }
    CP_COMMIT();

    for (int bi = 0; bi < NBLK; bi++) {
        const int s = bi & 1;
        CP_WAIT(0);
        __syncthreads();

        if (bi + 1 < NBLK) {
            const uint32_t st = (uint32_t)((1 - s) * KVSTG);
#pragma unroll
            for (int it = 0; it < 9; it++) {
                int id = tid + it * 256;
                int arr = id / 1152;
                int rem = id - arr * 1152;
                int row = rem / 12;
                int c   = rem - row * 12;
                const __half* src = (arr == 0 ? kf : vf)
                    + ((long)((bi + 1) * 96 + row) * NHEADS_ + n) * HP_ + c * 8;
                cp16(sbase + st + arr * KVARR + row * SSTB + c * 16, src);
            }
            CP_COMMIT();
        }

        float sacc[12][4];
#pragma unroll
        for (int f = 0; f < 12; f++)
#pragma unroll
            for (int e = 0; e < 4; e++) sacc[f][e] = 0.f;

        uint32_t kb = sbase + s * KVSTG;
#pragma unroll
        for (int kk = 0; kk < 6; kk++) {
            uint32_t ka = kb + (lane & 15) * SSTB + (lane >> 4) * 16 + kk * 32;
#pragma unroll
            for (int p = 0; p < 6; p++) {
                uint32_t rh[4];
                ldsm_x4(rh, ka + p * (16 * SSTB));
                uint32_t b0[2] = {rh[0], rh[2]}, b1[2] = {rh[1], rh[3]};
                mma_f16(sacc[2 * p + 0], qh[kk], b0);
                mma_f16(sacc[2 * p + 1], qh[kk], b1);
            }
        }

        if (bi == NBLK - 1) {
#pragma unroll
            for (int f = 2; f < 12; f++)
#pragma unroll
                for (int e = 0; e < 4; e++) sacc[f][e] = -120.f;
        }

        uint32_t vb = kb + KVARR;
#pragma unroll
        for (int kk = 0; kk < 6; kk++) {
            uint32_t pf[4];
            pf[0] = ex2h2(pack2h(sacc[2 * kk][0],     sacc[2 * kk][1]));
            pf[1] = ex2h2(pack2h(sacc[2 * kk][2],     sacc[2 * kk][3]));
            pf[2] = ex2h2(pack2h(sacc[2 * kk + 1][0], sacc[2 * kk + 1][1]));
            pf[3] = ex2h2(pack2h(sacc[2 * kk + 1][2], sacc[2 * kk + 1][3]));

            uint32_t va = vb + (kk * 16 + (lane & 15)) * SSTB + (lane >> 4) * 16;
#pragma unroll
            for (int j2 = 0; j2 < 6; j2++) {
                uint32_t th[4];
                ldsm_x4_t(th, va + j2 * 32);
                mma_f16(oacc[2 * j2 + 0], pf, &th[0]);
                mma_f16(oacc[2 * j2 + 1], pf, &th[2]);
            }
        }
    }

    float sumA = __shfl_sync(0xffffffffu, oacc[11][0], lane & ~3);
    float sumB = __shfl_sync(0xffffffffu, oacc[11][2], lane & ~3);
    float invA = 1.f / sumA;
    float invB = 1.f / sumB;
    int rA = q0 + wid * 16 + (lane >> 2);
    int rB = rA + 8;
#pragma unroll
    for (int f = 0; f < 11; f++) {
        int h = n * HD_ + f * 8 + (lane & 3) * 2;
        if (rA < T_)
            *(uint32_t*)(Of + (long)rA * NH_ + h) =
                pack2h(oacc[f][0] * invA, oacc[f][1] * invA);
        if (rB < T_)
            *(uint32_t*)(Of + (long)rB * NH_ + h) =
                pack2h(oacc[f][2] * invB, oacc[f][3] * invB);
    }
}

// ---------------------------------------------------------------------------
extern "C" void kernel_launch(void* const* d_in, const int* in_sizes, int n_in,
                              void* d_out, int out_size)
{
    const float* x  = (const float*)d_in[0];
    const float* fc = (const float*)d_in[1];
    const float* Wq = (const float*)d_in[2];
    const float* bq = (const float*)d_in[3];
    const float* Wk = (const float*)d_in[4];
    const float* bk = (const float*)d_in[5];
    const float* Wv = (const float*)d_in[6];
    const float* bv = (const float*)d_in[7];
    const float* Wo = (const float*)d_in[8];
    const float* bo = (const float*)d_in[9];
    float* out = (float*)d_out;

    __half *xf, *af, *wf, *qf, *kf, *vf;
    cudaGetSymbolAddress((void**)&xf, g_xf);
    cudaGetSymbolAddress((void**)&af, g_af);
    cudaGetSymbolAddress((void**)&wf, g_wf);
    cudaGetSymbolAddress((void**)&qf, g_qf);
    cudaGetSymbolAddress((void**)&kf, g_kf);
    cudaGetSymbolAddress((void**)&vf, g_vf);

    const long WSZ = (long)GK_ * GN_;
    const long totalCvt = (long)(T_ * GK_ / 2) + 4L * (WSZ / 2);

    pad_kernel<<<(PAD_R1 + PAD_R2 + 255) / 256, 256>>>(qf, kf, vf);
    cvt_all_kernel<<<(int)((totalCvt + 255) / 256), 256>>>(x, Wq, Wk, Wv, Wo, xf, wf);

    cudaFuncSetAttribute(hmma_gemm10_kernel,
                         cudaFuncAttributeMaxDynamicSharedMemorySize, GEMM_SMEM);
    cudaFuncSetAttribute(hmma_attn_kernel,
                         cudaFuncAttributeMaxDynamicSharedMemorySize, ATT_SMEM);

    // fused QKV GEMM + RoPE (+SL2 on Q) epilogue — 64-row tiles, grid 33x32
    G3 gq;
    gq.bw[0] = wf + 0 * WSZ; gq.bias[0] = bq; gq.o0[0] = qf;
    gq.bw[1] = wf + 1 * WSZ; gq.bias[1] = bk; gq.o0[1] = kf;
    gq.bw[2] = wf + 2 * WSZ; gq.bias[2] = bv; gq.o0[2] = vf;
    gq.c0 = nullptr; gq.mode = 0;
    hmma_gemm10_kernel<<<dim3(33, 32), 256, GEMM_SMEM>>>(xf, fc, gq);

    // HMMA flash attention (side-channel softmax)
    hmma_attn_kernel<<<dim3(16, 16), 256, ATT_SMEM>>>(qf, kf, vf, af);

    // out-proj — 64-row tiles, grid 11x32 = 352 CTAs -> single wave at occ 3
    G3 go;
    go.bw[0] = go.bw[1] = go.bw[2] = wf + 3 * WSZ;
    go.bias[0] = go.bias[1] = go.bias[2] = bo;
    go.o0[0] = go.o0[1] = go.o0[2] = nullptr;
    go.c0 = out; go.mode = 1;
    hmma_gemm10_kernel<<<dim3(11, 32), 256, GEMM_SMEM>>>(af, fc, go);
}

// round 17
// speedup vs baseline: 1.0718x; 1.0718x over previous
#include <cuda_runtime.h>
#include <cuda_fp16.h>
#include <cstdint>
#include <math.h>

#define T_ 2032
#define TKV_ 2112            // keys padded to 22 * 96
#define D_ 1408
#define NH_ 1408
#define NHEADS_ 16
#define HD_ 88
#define HP_ 96
#define GK_ 1408
#define GN_ 1408
#define NCHUNK 88            // 1408 / 16
#define SL2 0.15379179f      // 88^-0.5 * log2(e)

// Scratch (allocation-free rule: device globals), all fp16
__device__ __half g_xf[T_ * GK_];                 // x rounded (A of QKV)
__device__ __half g_af[T_ * GK_];                 // attn-out rounded (A of out-proj)
__device__ __half g_wf[4L * GK_ * GN_];           // Wq|Wk|Wv|Wo rounded
#define PADSZ (TKV_ * NHEADS_ * HP_)
__device__ __half g_qf[PADSZ];                    // pre-scaled by SL2; col89 = -8
__device__ __half g_kf[PADSZ];                    // col89 = 1
__device__ __half g_vf[PADSZ];                    // col88 = 1 (row-sum column)

// ===========================================================================
// Helpers (baseline PTX — compute_103 safe)
// ===========================================================================
__device__ __forceinline__ uint32_t smem_u32(const void* p) {
    uint32_t a;
    asm("{ .reg .u64 t; cvta.to.shared.u64 t, %1; cvt.u32.u64 %0, t; }"
        : "=r"(a) : "l"(p));
    return a;
}
__device__ __forceinline__ void ldsm_x4(uint32_t* r, uint32_t addr) {
    asm volatile("ldmatrix.sync.aligned.m8n8.x4.shared.b16 {%0,%1,%2,%3}, [%4];"
                 : "=r"(r[0]), "=r"(r[1]), "=r"(r[2]), "=r"(r[3]) : "r"(addr));
}
__device__ __forceinline__ void ldsm_x4_t(uint32_t* r, uint32_t addr) {
    asm volatile("ldmatrix.sync.aligned.m8n8.x4.trans.shared.b16 {%0,%1,%2,%3}, [%4];"
                 : "=r"(r[0]), "=r"(r[1]), "=r"(r[2]), "=r"(r[3]) : "r"(addr));
}
__device__ __forceinline__ void mma_f16(float* d, const uint32_t* a, const uint32_t* b) {
    asm volatile(
        "mma.sync.aligned.m16n8k16.row.col.f32.f16.f16.f32 "
        "{%0,%1,%2,%3}, {%4,%5,%6,%7}, {%8,%9}, {%0,%1,%2,%3};"
        : "+f"(d[0]), "+f"(d[1]), "+f"(d[2]), "+f"(d[3])
        : "r"(a[0]), "r"(a[1]), "r"(a[2]), "r"(a[3]), "r"(b[0]), "r"(b[1]));
}
__device__ __forceinline__ uint32_t ex2h2(uint32_t a) {
    uint32_t y;
    asm("ex2.approx.f16x2 %0, %1;" : "=r"(y) : "r"(a));
    return y;
}
__device__ __forceinline__ void cp16(uint32_t dst, const void* src) {
    asm volatile("cp.async.cg.shared.global [%0], [%1], 16;"
                 :: "r"(dst), "l"(src) : "memory");
}
__device__ __forceinline__ void cp16z(uint32_t dst, const void* src, uint32_t srcsz) {
    asm volatile("cp.async.cg.shared.global [%0], [%1], 16, %2;"
                 :: "r"(dst), "l"(src), "r"(srcsz) : "memory");
}
#define CP_COMMIT() asm volatile("cp.async.commit_group;" ::: "memory")
#define CP_WAIT(n)  asm volatile("cp.async.wait_group %0;" :: "n"(n) : "memory")

__device__ __forceinline__ uint32_t pack2h(float x, float y) {
    return (uint32_t)__half_as_ushort(__float2half_rn(x))
         | ((uint32_t)__half_as_ushort(__float2half_rn(y)) << 16);
}

// ===========================================================================
// Prep: pad + side-channel constants + x/weights conversion, ONE launch.
// ===========================================================================
#define PAD_R1 (TKV_ * NHEADS_ * 4)
#define PAD_R2 ((TKV_ - T_) * NHEADS_ * 44)
#define PAD_N  (PAD_R1 + PAD_R2)

__global__ void prep_all_kernel(const float* __restrict__ x,
                                const float* __restrict__ w0, const float* __restrict__ w1,
                                const float* __restrict__ w2, const float* __restrict__ w3,
                                __half* __restrict__ xf, __half* __restrict__ wf,
                                __half* __restrict__ qf, __half* __restrict__ kf,
                                __half* __restrict__ vf)
{
    long i = (long)blockIdx.x * 256 + threadIdx.x;
    const int n2x = T_ * GK_ / 2;
    const long n2w = (long)GK_ * GN_ / 2;

    if (i < PAD_N) {
        uint32_t idx;
        uint32_t qv = 0, kv = 0, vv = 0;
        if (i < PAD_R1) {
            int th = (int)(i >> 2), off = (int)(i & 3);
            idx = (uint32_t)th * 48 + 44 + off;
            if (off == 0) {             // cols (88, 89)
                qv = pack2h(0.f, -8.f);
                kv = pack2h(0.f, 1.f);
                vv = pack2h(1.f, 0.f);
            }
        } else {
            int j = (int)(i - PAD_R1);
            int t = T_ + j / (NHEADS_ * 44);
            int r = j % (NHEADS_ * 44);
            int head = r / 44, p = r % 44;
            idx = (uint32_t)(t * NHEADS_ + head) * 48 + p;
        }
        ((uint32_t*)qf)[idx] = qv; ((uint32_t*)kf)[idx] = kv;
        ((uint32_t*)vf)[idx] = vv;
        return;
    }
    i -= PAD_N;
    if (i < n2x) {
        float2 v = ((const float2*)x)[i];
        ((uint32_t*)xf)[i] = pack2h(v.x, v.y);
        return;
    }
    long j = i - n2x;
    if (j >= 4 * n2w) return;
    int which = (int)(j / n2w);
    long r = j - (long)which * n2w;
    const float* src = which == 0 ? w0 : which == 1 ? w1 : which == 2 ? w2 : w3;
    float2 v = ((const float2*)src)[r];
    ((uint32_t*)wf)[j] = pack2h(v.x, v.y);
}

// ===========================================================================
// Shared G3 struct
// ===========================================================================
struct G3 {
    const __half* bw[3];
    const float* bias[3];
    __half* o0[3];
    float* c0;
    int mode;
};

#define AS_ST 24        // halfs per A smem row (48 B)
#define BS_ST 136       // halfs per B smem row (272 B)

// ===========================================================================
// HMMA GEMM v9: 128x128 CTA tile, occ 2 (QKV — measured near floor)
// ===========================================================================
#define GBUF9 10496
#define GEMM9_SMEM (4 * GBUF9)   // 41984

__global__ __launch_bounds__(256, 2)
void hmma_gemm9_kernel(const __half* __restrict__ Ah,
                       const float* __restrict__ fc, G3 g)
{
    extern __shared__ char smg[];
    uint32_t sb = smem_u32(smg);

    const int tid = threadIdx.x;
    const int wid = tid >> 5, lane = tid & 31;
    const int wm = wid & 3, wn = wid >> 2;
    const int bm = blockIdx.y * 128;
    const int which = blockIdx.x / 11;
    const int bn = (blockIdx.x - which * 11) * 128;

    const int arow = tid >> 1;
    const int acs = (tid & 1) * 8;
    const int brow = tid >> 4;
    const int bcs = (tid & 15) * 8;
    const uint32_t aok = ((bm + arow) < T_) ? 16u : 0u;

    const __half* ag = Ah + (long)(bm + arow) * GK_ + acs;
    const __half* bg = g.bw[which] + (long)brow * GN_ + bn + bcs;

    const uint32_t a_dst = sb + (uint32_t)((arow * AS_ST + acs) * 2);
    const uint32_t b_dst = sb + 6144u + (uint32_t)((brow * BS_ST + bcs) * 2);

    float acc[2][8][4];
#pragma unroll
    for (int i = 0; i < 2; i++)
#pragma unroll
        for (int j = 0; j < 8; j++)
#pragma unroll
            for (int e = 0; e < 4; e++) acc[i][j][e] = 0.f;

    const uint32_t aoff = (uint32_t)((wm * 32 + (lane & 15)) * 48 + (lane >> 4) * 16);
    const uint32_t boff = (uint32_t)((lane & 15) * 272 + wn * 128 + (lane >> 4) * 16);

#pragma unroll
    for (int c = 0; c < 3; c++) {
        cp16z(a_dst + c * GBUF9, ag + c * 16, aok);
        cp16(b_dst + c * GBUF9, bg + (long)(c * 16) * GN_);
        CP_COMMIT();
    }

    for (int c = 0; c < NCHUNK; c++) {
        const int s = c & 3;
        if (c <= NCHUNK - 3)      { CP_WAIT(2); }
        else if (c == NCHUNK - 2) { CP_WAIT(1); }
        else                      { CP_WAIT(0); }
        __syncthreads();

        if (c + 3 < NCHUNK) {
            const uint32_t st = (uint32_t)(((c + 3) & 3) * GBUF9);
            cp16z(a_dst + st, ag + (c + 3) * 16, aok);
            cp16(b_dst + st, bg + (long)((c + 3) * 16) * GN_);
            CP_COMMIT();
        }

        uint32_t ah[2][4], bh[4][4];
        {
            uint32_t a_b = sb + s * GBUF9;
#pragma unroll
            for (int i = 0; i < 2; i++)
                ldsm_x4(ah[i], a_b + aoff + i * 16 * 48);
            uint32_t b_b = sb + s * GBUF9 + 6144;
#pragma unroll
            for (int j2 = 0; j2 < 4; j2++)
                ldsm_x4_t(bh[j2], b_b + boff + j2 * 32);
        }
#pragma unroll
        for (int i = 0; i < 2; i++)
#pragma unroll
            for (int j = 0; j < 8; j++)
                mma_f16(acc[i][j], ah[i], &bh[j >> 1][(j & 1) * 2]);
    }

    const float* bias = g.bias[which];
    {
        __half* o0 = g.o0[which];
        const bool dorope = (which < 2);
        const float qs = (which == 0) ? SL2 : 1.0f;
#pragma unroll
        for (int i = 0; i < 2; i++) {
            int r0 = bm + wm * 32 + i * 16 + (lane >> 2);
#pragma unroll
            for (int j = 0; j < 8; j++) {
                int cc = bn + wn * 64 + j * 8 + (lane & 3) * 2;
                float b0 = bias[cc], b1 = bias[cc + 1];
                int head = cc / HD_;
                int h = cc - head * HD_;
#pragma unroll
                for (int half = 0; half < 2; half++) {
                    int t = r0 + half * 8;
                    if (t >= T_) continue;
                    float v0 = acc[i][j][2 * half + 0] + b0;
                    float v1 = acc[i][j][2 * half + 1] + b1;
                    float r0v = v0, r1v = v1;
                    if (dorope) {
                        float cs = fc[t * HD_ + h];
                        float sn = fc[t * HD_ + h + 1];
                        r0v = v0 * cs - v1 * sn;
                        r1v = v0 * sn + v1 * cs;
                    }
                    r0v *= qs; r1v *= qs;
                    uint32_t dst = (uint32_t)(t * NHEADS_ + head) * HP_ + h;
                    *(uint32_t*)(o0 + dst) = pack2h(r0v, r1v);
                }
            }
        }
    }
}

// ===========================================================================
// HMMA GEMM v10: 64x128 CTA tile, occ 3 (out-proj — single-wave packing)
// ===========================================================================
#define ABYT 3072
#define GBUF10 7424
#define GEMM10_SMEM (4 * GBUF10)   // 29696

__global__ __launch_bounds__(256, 3)
void hmma_gemm10_kernel(const __half* __restrict__ Ah,
                        const __half* __restrict__ Bw,
                        const float* __restrict__ bias, float* __restrict__ C)
{
    extern __shared__ char smg[];
    uint32_t sb = smem_u32(smg);

    const int tid = threadIdx.x;
    const int wid = tid >> 5, lane = tid & 31;
    const int wm = wid & 3, wn = wid >> 2;
    const int bm = blockIdx.y * 64;
    const int bn = blockIdx.x * 128;

    const int arow = tid >> 1;
    const int acs = (tid & 1) * 8;
    const int brow = tid >> 4;
    const int bcs = (tid & 15) * 8;
    const bool hasA = tid < 128;
    const uint32_t aok = (hasA && (bm + arow) < T_) ? 16u : 0u;

    const __half* ag = Ah + (long)(bm + arow) * GK_ + acs;
    const __half* bg = Bw + (long)brow * GN_ + bn + bcs;

    const uint32_t a_dst = sb + (uint32_t)((arow * AS_ST + acs) * 2);
    const uint32_t b_dst = sb + ABYT + (uint32_t)((brow * BS_ST + bcs) * 2);

    float acc[8][4];
#pragma unroll
    for (int j = 0; j < 8; j++)
#pragma unroll
        for (int e = 0; e < 4; e++) acc[j][e] = 0.f;

    const uint32_t aoff = (uint32_t)((wm * 16 + (lane & 15)) * 48 + (lane >> 4) * 16);
    const uint32_t boff = (uint32_t)((lane & 15) * 272 + wn * 128 + (lane >> 4) * 16);

#pragma unroll
    for (int c = 0; c < 3; c++) {
        if (hasA) cp16z(a_dst + c * GBUF10, ag + c * 16, aok);
        cp16(b_dst + c * GBUF10, bg + (long)(c * 16) * GN_);
        CP_COMMIT();
    }

    for (int c = 0; c < NCHUNK; c++) {
        const int s = c & 3;
        if (c <= NCHUNK - 3)      { CP_WAIT(2); }
        else if (c == NCHUNK - 2) { CP_WAIT(1); }
        else                      { CP_WAIT(0); }
        __syncthreads();

        if (c + 3 < NCHUNK) {
            const uint32_t st = (uint32_t)(((c + 3) & 3) * GBUF10);
            if (hasA) cp16z(a_dst + st, ag + (c + 3) * 16, aok);
            cp16(b_dst + st, bg + (long)((c + 3) * 16) * GN_);
            CP_COMMIT();
        }

        uint32_t ah[4], bh[4][4];
        {
            uint32_t a_b = sb + s * GBUF10;
            ldsm_x4(ah, a_b + aoff);
            uint32_t b_b = sb + s * GBUF10 + ABYT;
#pragma unroll
            for (int j2 = 0; j2 < 4; j2++)
                ldsm_x4_t(bh[j2], b_b + boff + j2 * 32);
        }
#pragma unroll
        for (int j = 0; j < 8; j++)
            mma_f16(acc[j], ah, &bh[j >> 1][(j & 1) * 2]);
    }

    int r0 = bm + wm * 16 + (lane >> 2);
#pragma unroll
    for (int j = 0; j < 8; j++) {
        int cc = bn + wn * 64 + j * 8 + (lane & 3) * 2;
        float b0 = bias[cc], b1 = bias[cc + 1];
        if (r0 < T_) {
            float* p = C + (long)r0 * GN_ + cc;
            p[0] = acc[j][0] + b0;
            p[1] = acc[j][1] + b1;
        }
        if (r0 + 8 < T_) {
            float* p = C + (long)(r0 + 8) * GN_ + cc;
            p[0] = acc[j][2] + b0;
            p[1] = acc[j][3] + b1;
        }
    }
}

// ===========================================================================
// HMMA flash attention v6 (unchanged — at MMA floor)
// ===========================================================================
#define SSTB 208
#define KVARR 19968
#define KVSTG (2 * KVARR)
#define ATT_SMEM (2 * KVSTG) // 79872
#define NBLK 22

__global__ __launch_bounds__(256, 2)
void hmma_attn_kernel(const __half* __restrict__ qf,
                      const __half* __restrict__ kf,
                      const __half* __restrict__ vf,
                      __half* __restrict__ Of)
{
    extern __shared__ char sm[];
    uint32_t sbase = smem_u32(sm);
    const int tid = threadIdx.x;
    const int wid = tid >> 5;
    const int lane = tid & 31;
    const int n = blockIdx.y;
    const int q0 = blockIdx.x * 128;

#pragma unroll
    for (int it = 0; it < 6; it++) {
        int id = tid + it * 256;
        int row = id / 12;
        int c   = id - row * 12;
        const __half* src = qf + ((long)(q0 + row) * NHEADS_ + n) * HP_ + c * 8;
        cp16(sbase + row * SSTB + c * 16, src);
    }
    CP_COMMIT();
    CP_WAIT(0);
    __syncthreads();

    uint32_t qh[6][4];
    {
        uint32_t qaddr = sbase + (wid * 16 + (lane & 15)) * SSTB + (lane >> 4) * 16;
#pragma unroll
        for (int kk = 0; kk < 6; kk++)
            ldsm_x4(qh[kk], qaddr + kk * 32);
    }
    __syncthreads();

    float oacc[12][4];
#pragma unroll
    for (int f = 0; f < 12; f++)
#pragma unroll
        for (int e = 0; e < 4; e++) oacc[f][e] = 0.f;

#pragma unroll
    for (int it = 0; it < 9; it++) {
        int id = tid + it * 256;
        int arr = id / 1152;
        int rem = id - arr * 1152;
        int row = rem / 12;
        int c   = rem - row * 12;
        const __half* src = (arr == 0 ? kf : vf)
            + ((long)row * NHEADS_ + n) * HP_ + c * 8;
        cp16(sbase + arr * KVARR + row * SSTB + c * 16, src);
    }
    CP_COMMIT();

    for (int bi = 0; bi < NBLK; bi++) {
        const int s = bi & 1;
        CP_WAIT(0);
        __syncthreads();

        if (bi + 1 < NBLK) {
            const uint32_t st = (uint32_t)((1 - s) * KVSTG);
#pragma unroll
            for (int it = 0; it < 9; it++) {
                int id = tid + it * 256;
                int arr = id / 1152;
                int rem = id - arr * 1152;
                int row = rem / 12;
                int c   = rem - row * 12;
                const __half* src = (arr == 0 ? kf : vf)
                    + ((long)((bi + 1) * 96 + row) * NHEADS_ + n) * HP_ + c * 8;
                cp16(sbase + st + arr * KVARR + row * SSTB + c * 16, src);
            }
            CP_COMMIT();
        }

        float sacc[12][4];
#pragma unroll
        for (int f = 0; f < 12; f++)
#pragma unroll
            for (int e = 0; e < 4; e++) sacc[f][e] = 0.f;

        uint32_t kb = sbase + s * KVSTG;
#pragma unroll
        for (int kk = 0; kk < 6; kk++) {
            uint32_t ka = kb + (lane & 15) * SSTB + (lane >> 4) * 16 + kk * 32;
#pragma unroll
            for (int p = 0; p < 6; p++) {
                uint32_t rh[4];
                ldsm_x4(rh, ka + p * (16 * SSTB));
                uint32_t b0[2] = {rh[0], rh[2]}, b1[2] = {rh[1], rh[3]};
                mma_f16(sacc[2 * p + 0], qh[kk], b0);
                mma_f16(sacc[2 * p + 1], qh[kk], b1);
            }
        }

        if (bi == NBLK - 1) {
#pragma unroll
            for (int f = 2; f < 12; f++)
#pragma unroll
                for (int e = 0; e < 4; e++) sacc[f][e] = -120.f;
        }

        uint32_t vb = kb + KVARR;
#pragma unroll
        for (int kk = 0; kk < 6; kk++) {
            uint32_t pf[4];
            pf[0] = ex2h2(pack2h(sacc[2 * kk][0],     sacc[2 * kk][1]));
            pf[1] = ex2h2(pack2h(sacc[2 * kk][2],     sacc[2 * kk][3]));
            pf[2] = ex2h2(pack2h(sacc[2 * kk + 1][0], sacc[2 * kk + 1][1]));
            pf[3] = ex2h2(pack2h(sacc[2 * kk + 1][2], sacc[2 * kk + 1][3]));

            uint32_t va = vb + (kk * 16 + (lane & 15)) * SSTB + (lane >> 4) * 16;
#pragma unroll
            for (int j2 = 0; j2 < 6; j2++) {
                uint32_t th[4];
                ldsm_x4_t(th, va + j2 * 32);
                mma_f16(oacc[2 * j2 + 0], pf, &th[0]);
                mma_f16(oacc[2 * j2 + 1], pf, &th[2]);
            }
        }
    }

    float sumA = __shfl_sync(0xffffffffu, oacc[11][0], lane & ~3);
    float sumB = __shfl_sync(0xffffffffu, oacc[11][2], lane & ~3);
    float invA = 1.f / sumA;
    float invB = 1.f / sumB;
    int rA = q0 + wid * 16 + (lane >> 2);
    int rB = rA + 8;
#pragma unroll
    for (int f = 0; f < 11; f++) {
        int h = n * HD_ + f * 8 + (lane & 3) * 2;
        if (rA < T_)
            *(uint32_t*)(Of + (long)rA * NH_ + h) =
                pack2h(oacc[f][0] * invA, oacc[f][1] * invA);
        if (rB < T_)
            *(uint32_t*)(Of + (long)rB * NH_ + h) =
                pack2h(oacc[f][2] * invB, oacc[f][3] * invB);
    }
}

// ---------------------------------------------------------------------------
extern "C" void kernel_launch(void* const* d_in, const int* in_sizes, int n_in,
                              void* d_out, int out_size)
{
    const float* x  = (const float*)d_in[0];
    const float* fc = (const float*)d_in[1];
    const float* Wq = (const float*)d_in[2];
    const float* bq = (const float*)d_in[3];
    const float* Wk = (const float*)d_in[4];
    const float* bk = (const float*)d_in[5];
    const float* Wv = (const float*)d_in[6];
    const float* bv = (const float*)d_in[7];
    const float* Wo = (const float*)d_in[8];
    const float* bo = (const float*)d_in[9];
    float* out = (float*)d_out;

    __half *xf, *af, *wf, *qf, *kf, *vf;
    cudaGetSymbolAddress((void**)&xf, g_xf);
    cudaGetSymbolAddress((void**)&af, g_af);
    cudaGetSymbolAddress((void**)&wf, g_wf);
    cudaGetSymbolAddress((void**)&qf, g_qf);
    cudaGetSymbolAddress((void**)&kf, g_kf);
    cudaGetSymbolAddress((void**)&vf, g_vf);

    const long WSZ = (long)GK_ * GN_;
    const long totalPrep = (long)PAD_N + (long)(T_ * GK_ / 2) + 4L * (WSZ / 2);

    prep_all_kernel<<<(int)((totalPrep + 255) / 256), 256>>>(
        x, Wq, Wk, Wv, Wo, xf, wf, qf, kf, vf);

    cudaFuncSetAttribute(hmma_gemm9_kernel,
                         cudaFuncAttributeMaxDynamicSharedMemorySize, GEMM9_SMEM);
    cudaFuncSetAttribute(hmma_gemm10_kernel,
                         cudaFuncAttributeMaxDynamicSharedMemorySize, GEMM10_SMEM);
    cudaFuncSetAttribute(hmma_attn_kernel,
                         cudaFuncAttributeMaxDynamicSharedMemorySize, ATT_SMEM);

    // fused QKV GEMM + RoPE (+SL2 on Q) epilogue — 128x128 tiles (v9)
    G3 gq;
    gq.bw[0] = wf + 0 * WSZ; gq.bias[0] = bq; gq.o0[0] = qf;
    gq.bw[1] = wf + 1 * WSZ; gq.bias[1] = bk; gq.o0[1] = kf;
    gq.bw[2] = wf + 2 * WSZ; gq.bias[2] = bv; gq.o0[2] = vf;
    gq.c0 = nullptr; gq.mode = 0;
    hmma_gemm9_kernel<<<dim3(33, 16), 256, GEMM9_SMEM>>>(xf, fc, gq);

    // HMMA flash attention (side-channel softmax)
    hmma_attn_kernel<<<dim3(16, 16), 256, ATT_SMEM>>>(qf, kf, vf, af);

    // out-proj — 64x128 tiles (v10), 352 CTAs -> single wave at occ 3
    hmma_gemm10_kernel<<<dim3(11, 32), 256, GEMM10_SMEM>>>(af, wf + 3 * WSZ, bo, out);
}